// round 4
// baseline (speedup 1.0000x reference)
#include <cuda_runtime.h>
#include <math.h>
#include <stdint.h>

#define T_TOK 8192
#define H_DIM 1024
#define F_DIM 4096
#define E_NUM 8

// ---- scratch (static device globals; no allocation at launch time) ----
__device__ int      g_count[E_NUM];
__device__ int      g_off[E_NUM];
__device__ int      g_tok[E_NUM * T_TOK];
__device__ float    g_gate[E_NUM * T_TOK];
__device__ uint32_t g_sel[2 * T_TOK];                       // (expert<<16)|slot per token
__device__ float    g_hidden[(size_t)2 * T_TOK * F_DIM];    // fc1 output (268MB)
__device__ float    g_y[(size_t)2 * T_TOK * H_DIM];         // fc2 per-slot output (64MB)

__device__ __forceinline__ uint32_t f2tf32(float f) {
    uint32_t u; asm("cvt.rna.tf32.f32 %0, %1;" : "=r"(u) : "f"(f)); return u;
}

__device__ __forceinline__ void mma_tf32(float* c, const uint32_t* a, const uint32_t* b) {
    asm volatile(
        "mma.sync.aligned.m16n8k8.row.col.f32.tf32.tf32.f32 "
        "{%0,%1,%2,%3}, {%4,%5,%6,%7}, {%8,%9}, {%0,%1,%2,%3};"
        : "+f"(c[0]), "+f"(c[1]), "+f"(c[2]), "+f"(c[3])
        : "r"(a[0]), "r"(a[1]), "r"(a[2]), "r"(a[3]), "r"(b[0]), "r"(b[1]));
}

__device__ __forceinline__ float gelu_tanh(float v) {
    const float c = 0.7978845608028654f;
    float u = c * (v + 0.044715f * v * v * v);
    return 0.5f * v * (1.0f + tanhf(u));
}

// ======================= small kernels =======================
__global__ void zero_kernel() {
    if (threadIdx.x < E_NUM) g_count[threadIdx.x] = 0;
}

__global__ void router_kernel(const float* __restrict__ x, const float* __restrict__ rw) {
    int t = blockIdx.x * 8 + threadIdx.y;
    int lane = threadIdx.x;
    float acc[E_NUM];
#pragma unroll
    for (int e = 0; e < E_NUM; e++) acc[e] = 0.0f;
    const float* xrow = x + (size_t)t * H_DIM;
    for (int h = lane; h < H_DIM; h += 32) {
        float xv = xrow[h];
        const float4* r = (const float4*)(rw + (size_t)h * E_NUM);
        float4 r0 = r[0], r1 = r[1];
        acc[0] += xv * r0.x; acc[1] += xv * r0.y;
        acc[2] += xv * r0.z; acc[3] += xv * r0.w;
        acc[4] += xv * r1.x; acc[5] += xv * r1.y;
        acc[6] += xv * r1.z; acc[7] += xv * r1.w;
    }
#pragma unroll
    for (int e = 0; e < E_NUM; e++) {
#pragma unroll
        for (int off = 16; off > 0; off >>= 1)
            acc[e] += __shfl_xor_sync(0xffffffffu, acc[e], off);
    }
    if (lane == 0) {
        float m = acc[0];
#pragma unroll
        for (int e = 1; e < E_NUM; e++) m = fmaxf(m, acc[e]);
        float p[E_NUM]; float s = 0.0f;
#pragma unroll
        for (int e = 0; e < E_NUM; e++) { p[e] = expf(acc[e] - m); s += p[e]; }
        float inv = 1.0f / s;
        int i1 = 0; float v1 = p[0];
#pragma unroll
        for (int e = 1; e < E_NUM; e++) if (p[e] > v1) { v1 = p[e]; i1 = e; }
        int i2 = -1; float v2 = -1.0f;
#pragma unroll
        for (int e = 0; e < E_NUM; e++) if (e != i1 && p[e] > v2) { v2 = p[e]; i2 = e; }
        int s1 = atomicAdd(&g_count[i1], 1);
        g_tok[i1 * T_TOK + s1]  = t;
        g_gate[i1 * T_TOK + s1] = v1 * inv;
        g_sel[2 * t]            = ((uint32_t)i1 << 16) | (uint32_t)s1;
        int s2 = atomicAdd(&g_count[i2], 1);
        g_tok[i2 * T_TOK + s2]  = t;
        g_gate[i2 * T_TOK + s2] = v2 * inv;
        g_sel[2 * t + 1]        = ((uint32_t)i2 << 16) | (uint32_t)s2;
    }
}

__global__ void scan_kernel() {
    if (threadIdx.x == 0) {
        int s = 0;
#pragma unroll
        for (int e = 0; e < E_NUM; e++) { g_off[e] = s; s += g_count[e]; }
    }
}

// combine: out[t][h] = g1*y[r1][h] + g2*y[r2][h]  (float4, no atomics)
__global__ void combine_kernel(float* __restrict__ out) {
    int idx = blockIdx.x * 256 + threadIdx.x;        // over T*H/4
    int t  = idx >> (10 - 2);                        // / (H/4=256)
    int h4 = idx & 255;
    uint32_t va = g_sel[2 * t], vb = g_sel[2 * t + 1];
    int ea = va >> 16, sa = va & 0xFFFF;
    int eb = vb >> 16, sb = vb & 0xFFFF;
    float ga = g_gate[ea * T_TOK + sa];
    float gb = g_gate[eb * T_TOK + sb];
    size_t ra = (size_t)(g_off[ea] + sa) * H_DIM + h4 * 4;
    size_t rb = (size_t)(g_off[eb] + sb) * H_DIM + h4 * 4;
    float4 ya = *(const float4*)(g_y + ra);
    float4 yb = *(const float4*)(g_y + rb);
    float4 o;
    o.x = ga * ya.x + gb * yb.x;
    o.y = ga * ya.y + gb * yb.y;
    o.z = ga * ya.z + gb * yb.z;
    o.w = ga * ya.w + gb * yb.w;
    *(float4*)(out + (size_t)t * H_DIM + h4 * 4) = o;
}

// ======================= tensor-core grouped GEMM =======================
// 128x128 tile, BK=16, 256 threads (8 warps 2Mx4N), warp tile 64x32,
// mma.sync m16n8k8 tf32. Conflict-free smem:
//   A: m-major [128][20]  (pitch 20 % 32 -> frag banks 20g+k all distinct)
//   B: k-major [16][136]  (pitch 136 % 32=8 -> frag banks 8k+g all distinct)
template<int KTOT, int LDB, bool FC1>
__global__ void __launch_bounds__(256, 2)
moe_gemm(const float* __restrict__ Asrc, const float* __restrict__ W)
{
    const int e = blockIdx.z;
    const int n = g_count[e];
    const int row0 = blockIdx.y * 128;
    if (row0 >= n) return;
    const int col0 = blockIdx.x * 128;

    __shared__ uint32_t As[128][20];
    __shared__ uint32_t Bs[16][136];

    const int tid = threadIdx.x;
    const int lane = tid & 31;
    const int w = tid >> 5;
    const int wm = w & 1;        // 0..1  (64 rows)
    const int wn = w >> 1;       // 0..3  (32 cols)

    // ---- producer mapping ----
    // threads 0..127: A row (tid), 16 floats (4 x float4), 128B contiguous global
    // threads 128..255: B row (j&15), cols (j>>4)*16 .. +15, 64B contiguous global
    const bool isA = tid < 128;
    const float* gptr = nullptr;
    int srow = 0, scol = 0;
    if (isA) {
        srow = tid;
        if (row0 + srow < n) {
            if (FC1) gptr = Asrc + (size_t)g_tok[e * T_TOK + row0 + srow] * H_DIM;
            else     gptr = g_hidden + (size_t)(g_off[e] + row0 + srow) * F_DIM;
        }
    } else {
        int j = tid - 128;
        srow = j & 15;
        scol = (j >> 4) * 16;
        gptr = W + (size_t)e * KTOT * LDB + (size_t)srow * LDB + col0 + scol;
    }

    float acc[4][4][4];
#pragma unroll
    for (int i = 0; i < 4; i++)
#pragma unroll
        for (int j = 0; j < 4; j++)
#pragma unroll
            for (int q = 0; q < 4; q++) acc[i][j][q] = 0.0f;

    float4 rv[4];
    auto load_regs = [&](int k0) {
        if (isA) {
#pragma unroll
            for (int q = 0; q < 4; q++)
                rv[q] = gptr ? *(const float4*)(gptr + k0 + q * 4)
                             : make_float4(0.f, 0.f, 0.f, 0.f);
        } else {
            const float* p = gptr + (size_t)k0 * LDB;
#pragma unroll
            for (int q = 0; q < 4; q++)
                rv[q] = *(const float4*)(p + q * 4);
        }
    };
    auto store_smem = [&]() {
#pragma unroll
        for (int q = 0; q < 4; q++) {
            uint4 v = make_uint4(f2tf32(rv[q].x), f2tf32(rv[q].y),
                                 f2tf32(rv[q].z), f2tf32(rv[q].w));
            if (isA) *(uint4*)&As[srow][q * 4] = v;
            else     *(uint4*)&Bs[srow][scol + q * 4] = v;
        }
    };

    const int gq = lane >> 2;    // 0..7
    const int kq4 = lane & 3;    // 0..3

    load_regs(0);
    for (int k0 = 0; k0 < KTOT; k0 += 16) {
        store_smem();
        __syncthreads();
        if (k0 + 16 < KTOT) load_regs(k0 + 16);

#pragma unroll
        for (int kq = 0; kq < 16; kq += 8) {
            const int kr = kq + kq4;
            uint32_t af[4][4], bf[4][2];
#pragma unroll
            for (int mf = 0; mf < 4; mf++) {
                int m = wm * 64 + mf * 16 + gq;
                af[mf][0] = As[m][kr];
                af[mf][1] = As[m + 8][kr];
                af[mf][2] = As[m][kr + 4];
                af[mf][3] = As[m + 8][kr + 4];
            }
#pragma unroll
            for (int nf = 0; nf < 4; nf++) {
                int nn = wn * 32 + nf * 8 + gq;
                bf[nf][0] = Bs[kr][nn];
                bf[nf][1] = Bs[kr + 4][nn];
            }
#pragma unroll
            for (int mf = 0; mf < 4; mf++)
#pragma unroll
                for (int nf = 0; nf < 4; nf++)
                    mma_tf32(acc[mf][nf], af[mf], bf[nf]);
        }
        __syncthreads();
    }

    // ---- epilogue ----
    if (FC1) {
        const int hrow0 = g_off[e];
#pragma unroll
        for (int mf = 0; mf < 4; mf++) {
            int rlo = row0 + wm * 64 + mf * 16 + gq;
            int rhi = rlo + 8;
            float* dlo = g_hidden + (size_t)(hrow0 + rlo) * F_DIM;
            float* dhi = g_hidden + (size_t)(hrow0 + rhi) * F_DIM;
#pragma unroll
            for (int nf = 0; nf < 4; nf++) {
                int c = col0 + wn * 32 + nf * 8 + 2 * kq4;
                if (rlo < n) {
                    float2 v = make_float2(gelu_tanh(acc[mf][nf][0]),
                                           gelu_tanh(acc[mf][nf][1]));
                    *(float2*)(dlo + c) = v;
                }
                if (rhi < n) {
                    float2 v = make_float2(gelu_tanh(acc[mf][nf][2]),
                                           gelu_tanh(acc[mf][nf][3]));
                    *(float2*)(dhi + c) = v;
                }
            }
        }
    } else {
        const int yrow0 = g_off[e];
#pragma unroll
        for (int mf = 0; mf < 4; mf++) {
            int rlo = row0 + wm * 64 + mf * 16 + gq;
            int rhi = rlo + 8;
            float* dlo = g_y + (size_t)(yrow0 + rlo) * H_DIM;
            float* dhi = g_y + (size_t)(yrow0 + rhi) * H_DIM;
#pragma unroll
            for (int nf = 0; nf < 4; nf++) {
                int c = col0 + wn * 32 + nf * 8 + 2 * kq4;
                if (rlo < n)
                    *(float2*)(dlo + c) = make_float2(acc[mf][nf][0], acc[mf][nf][1]);
                if (rhi < n)
                    *(float2*)(dhi + c) = make_float2(acc[mf][nf][2], acc[mf][nf][3]);
            }
        }
    }
}

// ======================= launch =======================
extern "C" void kernel_launch(void* const* d_in, const int* in_sizes, int n_in,
                              void* d_out, int out_size) {
    const float* x  = (const float*)d_in[0];
    const float* rw = (const float*)d_in[1];
    const float* w1 = (const float*)d_in[2];
    const float* w2 = (const float*)d_in[3];
    float* out = (float*)d_out;

    zero_kernel<<<1, 32>>>();
    router_kernel<<<T_TOK / 8, dim3(32, 8)>>>(x, rw);
    scan_kernel<<<1, 32>>>();
    moe_gemm<H_DIM, F_DIM, true ><<<dim3(F_DIM / 128, T_TOK / 128, E_NUM), 256>>>(x, w1);
    moe_gemm<F_DIM, H_DIM, false><<<dim3(H_DIM / 128, T_TOK / 128, E_NUM), 256>>>(nullptr, w2);
    combine_kernel<<<(T_TOK * H_DIM / 4) / 256, 256>>>(out);
}

// round 5
// speedup vs baseline: 1.5613x; 1.5613x over previous
#include <cuda_runtime.h>
#include <math.h>
#include <stdint.h>

#define T_TOK 8192
#define H_DIM 1024
#define F_DIM 4096
#define E_NUM 8

// ---- scratch (static device globals; no allocation at launch time) ----
__device__ int      g_count[E_NUM];
__device__ int      g_off[E_NUM];
__device__ int      g_tok[E_NUM * T_TOK];
__device__ float    g_gate[E_NUM * T_TOK];
__device__ uint32_t g_sel[2 * T_TOK];                       // (expert<<16)|slot per token
__device__ float    g_hidden[(size_t)2 * T_TOK * F_DIM];    // fc1 output
__device__ float    g_y[(size_t)2 * T_TOK * H_DIM];         // fc2 per-slot output

__device__ __forceinline__ uint32_t f2tf32(float f) {
    uint32_t u; asm("cvt.rna.tf32.f32 %0, %1;" : "=r"(u) : "f"(f)); return u;
}

__device__ __forceinline__ void mma_tf32(float* c, const uint32_t* a, const uint32_t* b) {
    asm volatile(
        "mma.sync.aligned.m16n8k8.row.col.f32.tf32.tf32.f32 "
        "{%0,%1,%2,%3}, {%4,%5,%6,%7}, {%8,%9}, {%0,%1,%2,%3};"
        : "+f"(c[0]), "+f"(c[1]), "+f"(c[2]), "+f"(c[3])
        : "r"(a[0]), "r"(a[1]), "r"(a[2]), "r"(a[3]), "r"(b[0]), "r"(b[1]));
}

__device__ __forceinline__ float gelu_tanh(float v) {
    const float c = 0.7978845608028654f;
    float u = c * (v + 0.044715f * v * v * v);
    return 0.5f * v * (1.0f + tanhf(u));
}

// ======================= small kernels =======================
__global__ void zero_kernel() {
    if (threadIdx.x < E_NUM) g_count[threadIdx.x] = 0;
}

__global__ void router_kernel(const float* __restrict__ x, const float* __restrict__ rw) {
    int t = blockIdx.x * 8 + threadIdx.y;
    int lane = threadIdx.x;
    float acc[E_NUM];
#pragma unroll
    for (int e = 0; e < E_NUM; e++) acc[e] = 0.0f;
    const float* xrow = x + (size_t)t * H_DIM;
    for (int h = lane; h < H_DIM; h += 32) {
        float xv = xrow[h];
        const float4* r = (const float4*)(rw + (size_t)h * E_NUM);
        float4 r0 = r[0], r1 = r[1];
        acc[0] += xv * r0.x; acc[1] += xv * r0.y;
        acc[2] += xv * r0.z; acc[3] += xv * r0.w;
        acc[4] += xv * r1.x; acc[5] += xv * r1.y;
        acc[6] += xv * r1.z; acc[7] += xv * r1.w;
    }
#pragma unroll
    for (int e = 0; e < E_NUM; e++) {
#pragma unroll
        for (int off = 16; off > 0; off >>= 1)
            acc[e] += __shfl_xor_sync(0xffffffffu, acc[e], off);
    }
    if (lane == 0) {
        float m = acc[0];
#pragma unroll
        for (int e = 1; e < E_NUM; e++) m = fmaxf(m, acc[e]);
        float p[E_NUM]; float s = 0.0f;
#pragma unroll
        for (int e = 0; e < E_NUM; e++) { p[e] = expf(acc[e] - m); s += p[e]; }
        float inv = 1.0f / s;
        int i1 = 0; float v1 = p[0];
#pragma unroll
        for (int e = 1; e < E_NUM; e++) if (p[e] > v1) { v1 = p[e]; i1 = e; }
        int i2 = -1; float v2 = -1.0f;
#pragma unroll
        for (int e = 0; e < E_NUM; e++) if (e != i1 && p[e] > v2) { v2 = p[e]; i2 = e; }
        int s1 = atomicAdd(&g_count[i1], 1);
        g_tok[i1 * T_TOK + s1]  = t;
        g_gate[i1 * T_TOK + s1] = v1 * inv;
        g_sel[2 * t]            = ((uint32_t)i1 << 16) | (uint32_t)s1;
        int s2 = atomicAdd(&g_count[i2], 1);
        g_tok[i2 * T_TOK + s2]  = t;
        g_gate[i2 * T_TOK + s2] = v2 * inv;
        g_sel[2 * t + 1]        = ((uint32_t)i2 << 16) | (uint32_t)s2;
    }
}

__global__ void scan_kernel() {
    if (threadIdx.x == 0) {
        int s = 0;
#pragma unroll
        for (int e = 0; e < E_NUM; e++) { g_off[e] = s; s += g_count[e]; }
    }
}

// combine: out[t][h] = g1*y[r1][h] + g2*y[r2][h]  (float4, no atomics)
__global__ void combine_kernel(float* __restrict__ out) {
    int idx = blockIdx.x * 256 + threadIdx.x;
    int t  = idx >> 8;
    int h4 = idx & 255;
    uint32_t va = g_sel[2 * t], vb = g_sel[2 * t + 1];
    int ea = va >> 16, sa = va & 0xFFFF;
    int eb = vb >> 16, sb = vb & 0xFFFF;
    float ga = g_gate[ea * T_TOK + sa];
    float gb = g_gate[eb * T_TOK + sb];
    size_t ra = (size_t)(g_off[ea] + sa) * H_DIM + h4 * 4;
    size_t rb = (size_t)(g_off[eb] + sb) * H_DIM + h4 * 4;
    float4 ya = *(const float4*)(g_y + ra);
    float4 yb = *(const float4*)(g_y + rb);
    float4 o;
    o.x = ga * ya.x + gb * yb.x;
    o.y = ga * ya.y + gb * yb.y;
    o.z = ga * ya.z + gb * yb.z;
    o.w = ga * ya.w + gb * yb.w;
    *(float4*)(out + (size_t)t * H_DIM + h4 * 4) = o;
}

// ======================= tensor-core grouped GEMM =======================
// 128x128 tile, BK=16, 256 threads (8 warps 2Mx4N), warp tile 64x32,
// mma.sync m16n8k8 tf32. Double-buffered smem, one syncthreads/stage.
// Conflict-free CONSUMER layouts:
//   A: m-major [128][20]  (frag bank 20g+k -> all 32 distinct)
//   B: k-major [16][136]  (frag bank 8k+g  -> all 32 distinct)
// Coalesced PRODUCERS (round-3 mapping): A 2 thr/row, B 16 thr/row.
template<int KTOT, int LDB, bool FC1>
__global__ void __launch_bounds__(256, 2)
moe_gemm(const float* __restrict__ Asrc, const float* __restrict__ W)
{
    const int e = blockIdx.z;
    const int n = g_count[e];
    const int row0 = blockIdx.y * 128;
    if (row0 >= n) return;
    const int col0 = blockIdx.x * 128;

    __shared__ uint32_t As[2][128][20];
    __shared__ uint32_t Bs[2][16][136];

    const int tid = threadIdx.x;
    const int lane = tid & 31;
    const int w = tid >> 5;
    const int wm = w & 1;        // 0..1  (64 rows)
    const int wn = w >> 1;       // 0..3  (32 cols)

    // ---- producer mapping (coalesced) ----
    const int am = tid >> 1;             // A row 0..127, 2 threads/row
    const int ak = (tid & 1) * 8;        // k half
    const float* aptr = nullptr;
    if (row0 + am < n) {
        if (FC1) aptr = Asrc + (size_t)g_tok[e * T_TOK + row0 + am] * H_DIM + ak;
        else     aptr = g_hidden + (size_t)(g_off[e] + row0 + am) * F_DIM + ak;
    }
    const int bk = tid >> 4;             // B k-row 0..15
    const int bn = (tid & 15) * 8;       // col
    const float* bptr = W + (size_t)e * KTOT * LDB + (size_t)bk * LDB + col0 + bn;

    float acc[4][4][4];
#pragma unroll
    for (int i = 0; i < 4; i++)
#pragma unroll
        for (int j = 0; j < 4; j++)
#pragma unroll
            for (int q = 0; q < 4; q++) acc[i][j][q] = 0.0f;

    float4 ra0, ra1, rb0, rb1;
    auto load_regs = [&](int k0) {
        if (aptr) {
            ra0 = *(const float4*)(aptr + k0);
            ra1 = *(const float4*)(aptr + k0 + 4);
        } else {
            ra0 = make_float4(0.f, 0.f, 0.f, 0.f);
            ra1 = ra0;
        }
        const float* bp = bptr + (size_t)k0 * LDB;
        rb0 = *(const float4*)(bp);
        rb1 = *(const float4*)(bp + 4);
    };
    auto store_smem = [&](int st) {
        uint4 va0 = make_uint4(f2tf32(ra0.x), f2tf32(ra0.y), f2tf32(ra0.z), f2tf32(ra0.w));
        uint4 va1 = make_uint4(f2tf32(ra1.x), f2tf32(ra1.y), f2tf32(ra1.z), f2tf32(ra1.w));
        *(uint4*)&As[st][am][ak]     = va0;
        *(uint4*)&As[st][am][ak + 4] = va1;
        uint4 vb0 = make_uint4(f2tf32(rb0.x), f2tf32(rb0.y), f2tf32(rb0.z), f2tf32(rb0.w));
        uint4 vb1 = make_uint4(f2tf32(rb1.x), f2tf32(rb1.y), f2tf32(rb1.z), f2tf32(rb1.w));
        *(uint4*)&Bs[st][bk][bn]     = vb0;
        *(uint4*)&Bs[st][bk][bn + 4] = vb1;
    };

    const int gq = lane >> 2;    // 0..7
    const int kq4 = lane & 3;    // 0..3

    auto compute = [&](int st) {
#pragma unroll
        for (int kq = 0; kq < 16; kq += 8) {
            const int kr = kq + kq4;
            uint32_t af[4][4], bf[4][2];
#pragma unroll
            for (int mf = 0; mf < 4; mf++) {
                int m = wm * 64 + mf * 16 + gq;
                af[mf][0] = As[st][m][kr];
                af[mf][1] = As[st][m + 8][kr];
                af[mf][2] = As[st][m][kr + 4];
                af[mf][3] = As[st][m + 8][kr + 4];
            }
#pragma unroll
            for (int nf = 0; nf < 4; nf++) {
                int nn = wn * 32 + nf * 8 + gq;
                bf[nf][0] = Bs[st][kr][nn];
                bf[nf][1] = Bs[st][kr + 4][nn];
            }
#pragma unroll
            for (int mf = 0; mf < 4; mf++)
#pragma unroll
                for (int nf = 0; nf < 4; nf++)
                    mma_tf32(acc[mf][nf], af[mf], bf[nf]);
        }
    };

    constexpr int S = KTOT / 16;
    load_regs(0);
    store_smem(0);
    __syncthreads();
#pragma unroll 1
    for (int s = 0; s < S; s++) {
        if (s + 1 < S) load_regs((s + 1) * 16);
        compute(s & 1);
        if (s + 1 < S) store_smem((s + 1) & 1);
        __syncthreads();
    }

    // ---- epilogue ----
    if (FC1) {
        const int hrow0 = g_off[e];
#pragma unroll
        for (int mf = 0; mf < 4; mf++) {
            int rlo = row0 + wm * 64 + mf * 16 + gq;
            int rhi = rlo + 8;
            float* dlo = g_hidden + (size_t)(hrow0 + rlo) * F_DIM;
            float* dhi = g_hidden + (size_t)(hrow0 + rhi) * F_DIM;
#pragma unroll
            for (int nf = 0; nf < 4; nf++) {
                int c = col0 + wn * 32 + nf * 8 + 2 * kq4;
                if (rlo < n) {
                    float2 v = make_float2(gelu_tanh(acc[mf][nf][0]),
                                           gelu_tanh(acc[mf][nf][1]));
                    *(float2*)(dlo + c) = v;
                }
                if (rhi < n) {
                    float2 v = make_float2(gelu_tanh(acc[mf][nf][2]),
                                           gelu_tanh(acc[mf][nf][3]));
                    *(float2*)(dhi + c) = v;
                }
            }
        }
    } else {
        const int yrow0 = g_off[e];
#pragma unroll
        for (int mf = 0; mf < 4; mf++) {
            int rlo = row0 + wm * 64 + mf * 16 + gq;
            int rhi = rlo + 8;
            float* dlo = g_y + (size_t)(yrow0 + rlo) * H_DIM;
            float* dhi = g_y + (size_t)(yrow0 + rhi) * H_DIM;
#pragma unroll
            for (int nf = 0; nf < 4; nf++) {
                int c = col0 + wn * 32 + nf * 8 + 2 * kq4;
                if (rlo < n)
                    *(float2*)(dlo + c) = make_float2(acc[mf][nf][0], acc[mf][nf][1]);
                if (rhi < n)
                    *(float2*)(dhi + c) = make_float2(acc[mf][nf][2], acc[mf][nf][3]);
            }
        }
    }
}

// ======================= launch =======================
extern "C" void kernel_launch(void* const* d_in, const int* in_sizes, int n_in,
                              void* d_out, int out_size) {
    const float* x  = (const float*)d_in[0];
    const float* rw = (const float*)d_in[1];
    const float* w1 = (const float*)d_in[2];
    const float* w2 = (const float*)d_in[3];
    float* out = (float*)d_out;

    zero_kernel<<<1, 32>>>();
    router_kernel<<<T_TOK / 8, dim3(32, 8)>>>(x, rw);
    scan_kernel<<<1, 32>>>();
    moe_gemm<H_DIM, F_DIM, true ><<<dim3(F_DIM / 128, T_TOK / 128, E_NUM), 256>>>(x, w1);
    moe_gemm<F_DIM, H_DIM, false><<<dim3(H_DIM / 128, T_TOK / 128, E_NUM), 256>>>(nullptr, w2);
    combine_kernel<<<(T_TOK * H_DIM / 4) / 256, 256>>>(out);
}

// round 6
// speedup vs baseline: 1.5941x; 1.0210x over previous
#include <cuda_runtime.h>
#include <math.h>
#include <stdint.h>

#define T_TOK 8192
#define H_DIM 1024
#define F_DIM 4096
#define E_NUM 8

// ---- scratch (static device globals; no allocation at launch time) ----
__device__ int      g_count[E_NUM];
__device__ int      g_off[E_NUM];
__device__ int      g_tok[E_NUM * T_TOK];
__device__ float    g_gate[E_NUM * T_TOK];
__device__ uint32_t g_sel[2 * T_TOK];
__device__ float    g_hidden[(size_t)2 * T_TOK * F_DIM];    // fc1 out (pre-rounded)
__device__ float    g_y[(size_t)2 * T_TOK * H_DIM];         // fc2 per-slot out
__device__ float    g_xr[(size_t)T_TOK * H_DIM];            // rounded x
__device__ float    g_w1r[(size_t)E_NUM * H_DIM * F_DIM];   // rounded w1
__device__ float    g_w2r[(size_t)E_NUM * F_DIM * H_DIM];   // rounded w2

__device__ __forceinline__ void cp16(uint32_t dst, const float* src, uint32_t bytes) {
    asm volatile("cp.async.ca.shared.global [%0], [%1], 16, %2;"
                 :: "r"(dst), "l"(src), "r"(bytes) : "memory");
}
#define CP_COMMIT() asm volatile("cp.async.commit_group;" ::: "memory")
#define CP_WAIT(n)  asm volatile("cp.async.wait_group %0;" :: "n"(n) : "memory")

__device__ __forceinline__ void mma_tf32(float* c, const uint32_t* a, const uint32_t* b) {
    asm volatile(
        "mma.sync.aligned.m16n8k8.row.col.f32.tf32.tf32.f32 "
        "{%0,%1,%2,%3}, {%4,%5,%6,%7}, {%8,%9}, {%0,%1,%2,%3};"
        : "+f"(c[0]), "+f"(c[1]), "+f"(c[2]), "+f"(c[3])
        : "r"(a[0]), "r"(a[1]), "r"(a[2]), "r"(a[3]), "r"(b[0]), "r"(b[1]));
}

__device__ __forceinline__ float gelu_tanh(float v) {
    const float c = 0.7978845608028654f;
    float u = c * (v + 0.044715f * v * v * v);
    return 0.5f * v * (1.0f + tanhf(u));
}
// bits+0x1000 then tf32 HW truncation == cvt.rna.tf32 (round-nearest-away)
__device__ __forceinline__ float rna_bits(float v) {
    return __uint_as_float(__float_as_uint(v) + 0x1000u);
}

// ======================= small kernels =======================
__global__ void zero_kernel() {
    if (threadIdx.x < E_NUM) g_count[threadIdx.x] = 0;
}

// pre-round fp32 -> tf32-RNA carrier bits (low bits retained; mma truncates)
__global__ void round_kernel(const float* __restrict__ src, float* __restrict__ dst,
                             int n4) {
    int i = blockIdx.x * 256 + threadIdx.x;
    if (i < n4) {
        uint4 v = ((const uint4*)src)[i];
        v.x += 0x1000u; v.y += 0x1000u; v.z += 0x1000u; v.w += 0x1000u;
        ((uint4*)dst)[i] = v;
    }
}

__global__ void router_kernel(const float* __restrict__ x, const float* __restrict__ rw) {
    int t = blockIdx.x * 8 + threadIdx.y;
    int lane = threadIdx.x;
    float acc[E_NUM];
#pragma unroll
    for (int e = 0; e < E_NUM; e++) acc[e] = 0.0f;
    const float* xrow = x + (size_t)t * H_DIM;
    for (int h = lane; h < H_DIM; h += 32) {
        float xv = xrow[h];
        const float4* r = (const float4*)(rw + (size_t)h * E_NUM);
        float4 r0 = r[0], r1 = r[1];
        acc[0] += xv * r0.x; acc[1] += xv * r0.y;
        acc[2] += xv * r0.z; acc[3] += xv * r0.w;
        acc[4] += xv * r1.x; acc[5] += xv * r1.y;
        acc[6] += xv * r1.z; acc[7] += xv * r1.w;
    }
#pragma unroll
    for (int e = 0; e < E_NUM; e++) {
#pragma unroll
        for (int off = 16; off > 0; off >>= 1)
            acc[e] += __shfl_xor_sync(0xffffffffu, acc[e], off);
    }
    if (lane == 0) {
        float m = acc[0];
#pragma unroll
        for (int e = 1; e < E_NUM; e++) m = fmaxf(m, acc[e]);
        float p[E_NUM]; float s = 0.0f;
#pragma unroll
        for (int e = 0; e < E_NUM; e++) { p[e] = expf(acc[e] - m); s += p[e]; }
        float inv = 1.0f / s;
        int i1 = 0; float v1 = p[0];
#pragma unroll
        for (int e = 1; e < E_NUM; e++) if (p[e] > v1) { v1 = p[e]; i1 = e; }
        int i2 = -1; float v2 = -1.0f;
#pragma unroll
        for (int e = 0; e < E_NUM; e++) if (e != i1 && p[e] > v2) { v2 = p[e]; i2 = e; }
        int s1 = atomicAdd(&g_count[i1], 1);
        g_tok[i1 * T_TOK + s1]  = t;
        g_gate[i1 * T_TOK + s1] = v1 * inv;
        g_sel[2 * t]            = ((uint32_t)i1 << 16) | (uint32_t)s1;
        int s2 = atomicAdd(&g_count[i2], 1);
        g_tok[i2 * T_TOK + s2]  = t;
        g_gate[i2 * T_TOK + s2] = v2 * inv;
        g_sel[2 * t + 1]        = ((uint32_t)i2 << 16) | (uint32_t)s2;
    }
}

__global__ void scan_kernel() {
    if (threadIdx.x == 0) {
        int s = 0;
#pragma unroll
        for (int e = 0; e < E_NUM; e++) { g_off[e] = s; s += g_count[e]; }
    }
}

__global__ void combine_kernel(float* __restrict__ out) {
    int idx = blockIdx.x * 256 + threadIdx.x;
    int t  = idx >> 8;
    int h4 = idx & 255;
    uint32_t va = g_sel[2 * t], vb = g_sel[2 * t + 1];
    int ea = va >> 16, sa = va & 0xFFFF;
    int eb = vb >> 16, sb = vb & 0xFFFF;
    float ga = g_gate[ea * T_TOK + sa];
    float gb = g_gate[eb * T_TOK + sb];
    size_t ra = (size_t)(g_off[ea] + sa) * H_DIM + h4 * 4;
    size_t rb = (size_t)(g_off[eb] + sb) * H_DIM + h4 * 4;
    float4 ya = *(const float4*)(g_y + ra);
    float4 yb = *(const float4*)(g_y + rb);
    float4 o;
    o.x = ga * ya.x + gb * yb.x;
    o.y = ga * ya.y + gb * yb.y;
    o.z = ga * ya.z + gb * yb.z;
    o.w = ga * ya.w + gb * yb.w;
    *(float4*)(out + (size_t)t * H_DIM + h4 * 4) = o;
}

// ======================= tensor-core grouped GEMM =======================
// 128x128 tile, BK=16, 256 threads (8 warps 2Mx4N), warp tile 64x32.
// 4-stage cp.async pipeline; operands pre-rounded (no cvt in loop).
// Smem layouts (conflict-free consumer):
//   A: m-major pitch 20 words; B: k-major pitch 136 words.
#define A_STRIDE 10240u             // 128*20*4
#define B_OFF    40960u             // 4 * A_STRIDE
#define B_STRIDE 8704u              // 16*136*4
#define SMEM_BYTES (B_OFF + 4 * B_STRIDE)   // 75776

template<int KTOT, int LDB, bool FC1>
__global__ void __launch_bounds__(256, 2)
moe_gemm(const float* __restrict__ Asrc, const float* __restrict__ W)
{
    extern __shared__ char sm[];
    const int e = blockIdx.z;
    const int n = g_count[e];
    const int row0 = blockIdx.y * 128;
    if (row0 >= n) return;
    const int col0 = blockIdx.x * 128;

    const uint32_t sbase = (uint32_t)__cvta_generic_to_shared(sm);
    const int tid = threadIdx.x;
    const int lane = tid & 31;
    const int w = tid >> 5;
    const int wm = w & 1;
    const int wn = w >> 1;

    // ---- producer mapping (coalesced) ----
    const int am = tid >> 1;
    const int ak = (tid & 1) * 8;
    const float* aptr = Asrc;          // valid dummy for OOB (bytes=0)
    uint32_t abytes = 0;
    if (row0 + am < n) {
        abytes = 16;
        if (FC1) aptr = Asrc + (size_t)g_tok[e * T_TOK + row0 + am] * H_DIM + ak;
        else     aptr = g_hidden + (size_t)(g_off[e] + row0 + am) * F_DIM + ak;
    }
    const int bk = tid >> 4;
    const int bn = (tid & 15) * 8;
    const float* bptr = W + (size_t)e * KTOT * LDB + (size_t)bk * LDB + col0 + bn;

    const uint32_t dA = sbase + (uint32_t)(am * 20 + ak) * 4u;
    const uint32_t dB = sbase + B_OFF + (uint32_t)(bk * 136 + bn) * 4u;

    auto issue = [&](int s) {
        int st = s & 3;
        int k0 = s * 16;
        uint32_t da = dA + (uint32_t)st * A_STRIDE;
        cp16(da,      aptr + k0,     abytes);
        cp16(da + 16, aptr + k0 + 4, abytes);
        uint32_t db = dB + (uint32_t)st * B_STRIDE;
        const float* bp = bptr + (size_t)k0 * LDB;
        cp16(db,      bp,     16);
        cp16(db + 16, bp + 4, 16);
    };

    float acc[4][4][4];
#pragma unroll
    for (int i = 0; i < 4; i++)
#pragma unroll
        for (int j = 0; j < 4; j++)
#pragma unroll
            for (int q = 0; q < 4; q++) acc[i][j][q] = 0.0f;

    const int gq = lane >> 2;
    const int kq4 = lane & 3;

    auto compute = [&](int st) {
        const uint32_t* Asm = (const uint32_t*)(sm + st * A_STRIDE);
        const uint32_t* Bsm = (const uint32_t*)(sm + B_OFF + st * B_STRIDE);
#pragma unroll
        for (int kq = 0; kq < 16; kq += 8) {
            const int kr = kq + kq4;
            uint32_t af[4][4], bf[4][2];
#pragma unroll
            for (int mf = 0; mf < 4; mf++) {
                int m = wm * 64 + mf * 16 + gq;
                af[mf][0] = Asm[m * 20 + kr];
                af[mf][1] = Asm[(m + 8) * 20 + kr];
                af[mf][2] = Asm[m * 20 + kr + 4];
                af[mf][3] = Asm[(m + 8) * 20 + kr + 4];
            }
#pragma unroll
            for (int nf = 0; nf < 4; nf++) {
                int nn = wn * 32 + nf * 8 + gq;
                bf[nf][0] = Bsm[kr * 136 + nn];
                bf[nf][1] = Bsm[(kr + 4) * 136 + nn];
            }
#pragma unroll
            for (int mf = 0; mf < 4; mf++)
#pragma unroll
                for (int nf = 0; nf < 4; nf++)
                    mma_tf32(acc[mf][nf], af[mf], bf[nf]);
        }
    };

    constexpr int S = KTOT / 16;
    issue(0); CP_COMMIT();
    issue(1); CP_COMMIT();
    issue(2); CP_COMMIT();
#pragma unroll 1
    for (int s = 0; s < S; s++) {
        CP_WAIT(2);
        __syncthreads();
        if (s + 3 < S) issue(s + 3);
        CP_COMMIT();
        compute(s & 3);
    }

    // ---- epilogue ----
    if (FC1) {
        const int hrow0 = g_off[e];
#pragma unroll
        for (int mf = 0; mf < 4; mf++) {
            int rlo = row0 + wm * 64 + mf * 16 + gq;
            int rhi = rlo + 8;
            float* dlo = g_hidden + (size_t)(hrow0 + rlo) * F_DIM;
            float* dhi = g_hidden + (size_t)(hrow0 + rhi) * F_DIM;
#pragma unroll
            for (int nf = 0; nf < 4; nf++) {
                int c = col0 + wn * 32 + nf * 8 + 2 * kq4;
                if (rlo < n) {
                    float2 v = make_float2(rna_bits(gelu_tanh(acc[mf][nf][0])),
                                           rna_bits(gelu_tanh(acc[mf][nf][1])));
                    *(float2*)(dlo + c) = v;
                }
                if (rhi < n) {
                    float2 v = make_float2(rna_bits(gelu_tanh(acc[mf][nf][2])),
                                           rna_bits(gelu_tanh(acc[mf][nf][3])));
                    *(float2*)(dhi + c) = v;
                }
            }
        }
    } else {
        const int yrow0 = g_off[e];
#pragma unroll
        for (int mf = 0; mf < 4; mf++) {
            int rlo = row0 + wm * 64 + mf * 16 + gq;
            int rhi = rlo + 8;
            float* dlo = g_y + (size_t)(yrow0 + rlo) * H_DIM;
            float* dhi = g_y + (size_t)(yrow0 + rhi) * H_DIM;
#pragma unroll
            for (int nf = 0; nf < 4; nf++) {
                int c = col0 + wn * 32 + nf * 8 + 2 * kq4;
                if (rlo < n)
                    *(float2*)(dlo + c) = make_float2(acc[mf][nf][0], acc[mf][nf][1]);
                if (rhi < n)
                    *(float2*)(dhi + c) = make_float2(acc[mf][nf][2], acc[mf][nf][3]);
            }
        }
    }
}

// ======================= launch =======================
extern "C" void kernel_launch(void* const* d_in, const int* in_sizes, int n_in,
                              void* d_out, int out_size) {
    const float* x  = (const float*)d_in[0];
    const float* rw = (const float*)d_in[1];
    const float* w1 = (const float*)d_in[2];
    const float* w2 = (const float*)d_in[3];
    float* out = (float*)d_out;

    cudaFuncSetAttribute(moe_gemm<H_DIM, F_DIM, true>,
                         cudaFuncAttributeMaxDynamicSharedMemorySize, SMEM_BYTES);
    cudaFuncSetAttribute(moe_gemm<F_DIM, H_DIM, false>,
                         cudaFuncAttributeMaxDynamicSharedMemorySize, SMEM_BYTES);

    float* xr  = nullptr; cudaGetSymbolAddress((void**)&xr,  g_xr);
    float* w1r = nullptr; cudaGetSymbolAddress((void**)&w1r, g_w1r);
    float* w2r = nullptr; cudaGetSymbolAddress((void**)&w2r, g_w2r);

    zero_kernel<<<1, 32>>>();
    round_kernel<<<(T_TOK * H_DIM / 4 + 255) / 256, 256>>>(x, xr, T_TOK * H_DIM / 4);
    round_kernel<<<(E_NUM * H_DIM * F_DIM / 4 + 255) / 256, 256>>>(w1, w1r, E_NUM * H_DIM * F_DIM / 4);
    round_kernel<<<(E_NUM * F_DIM * H_DIM / 4 + 255) / 256, 256>>>(w2, w2r, E_NUM * F_DIM * H_DIM / 4);
    router_kernel<<<T_TOK / 8, dim3(32, 8)>>>(x, rw);
    scan_kernel<<<1, 32>>>();
    moe_gemm<H_DIM, F_DIM, true ><<<dim3(F_DIM / 128, T_TOK / 128, E_NUM), 256, SMEM_BYTES>>>(xr, w1r);
    moe_gemm<F_DIM, H_DIM, false><<<dim3(H_DIM / 128, T_TOK / 128, E_NUM), 256, SMEM_BYTES>>>(nullptr, w2r);
    combine_kernel<<<(T_TOK * H_DIM / 4) / 256, 256>>>(out);
}

// round 7
// speedup vs baseline: 1.7997x; 1.1290x over previous
#include <cuda_runtime.h>
#include <math.h>
#include <stdint.h>

#define T_TOK 8192
#define H_DIM 1024
#define F_DIM 4096
#define E_NUM 8

// ---- scratch (static device globals; no allocation at launch time) ----
__device__ int      g_count[E_NUM];
__device__ int      g_off[E_NUM];
__device__ int      g_tok[E_NUM * T_TOK];
__device__ float    g_gate[E_NUM * T_TOK];
__device__ uint32_t g_sel[2 * T_TOK];
__device__ float    g_hidden[(size_t)2 * T_TOK * F_DIM];    // fc1 out (pre-rounded)
__device__ float    g_y[(size_t)2 * T_TOK * H_DIM];         // fc2 per-slot out
__device__ float    g_xr[(size_t)T_TOK * H_DIM];            // rounded x
__device__ float    g_w1r[(size_t)E_NUM * H_DIM * F_DIM];   // rounded w1
__device__ float    g_w2r[(size_t)E_NUM * F_DIM * H_DIM];   // rounded w2

__device__ __forceinline__ void cp16(uint32_t dst, const float* src, uint32_t bytes) {
    asm volatile("cp.async.ca.shared.global [%0], [%1], 16, %2;"
                 :: "r"(dst), "l"(src), "r"(bytes) : "memory");
}
#define CP_COMMIT() asm volatile("cp.async.commit_group;" ::: "memory")
#define CP_WAIT(n)  asm volatile("cp.async.wait_group %0;" :: "n"(n) : "memory")

__device__ __forceinline__ void mma_tf32(float* c, const uint32_t* a, const uint32_t* b) {
    asm volatile(
        "mma.sync.aligned.m16n8k8.row.col.f32.tf32.tf32.f32 "
        "{%0,%1,%2,%3}, {%4,%5,%6,%7}, {%8,%9}, {%0,%1,%2,%3};"
        : "+f"(c[0]), "+f"(c[1]), "+f"(c[2]), "+f"(c[3])
        : "r"(a[0]), "r"(a[1]), "r"(a[2]), "r"(a[3]), "r"(b[0]), "r"(b[1]));
}

__device__ __forceinline__ float gelu_tanh(float v) {
    const float c = 0.7978845608028654f;
    float u = c * (v + 0.044715f * v * v * v);
    return 0.5f * v * (1.0f + tanhf(u));
}
// bits+0x1000 then tf32 HW truncation == cvt.rna.tf32
__device__ __forceinline__ float rna_bits(float v) {
    return __uint_as_float(__float_as_uint(v) + 0x1000u);
}

// ======================= small kernels =======================
__global__ void zero_kernel() {
    if (threadIdx.x < E_NUM) g_count[threadIdx.x] = 0;
}

__global__ void round_kernel(const float* __restrict__ src, float* __restrict__ dst,
                             int n4) {
    int i = blockIdx.x * 256 + threadIdx.x;
    if (i < n4) {
        uint4 v = ((const uint4*)src)[i];
        v.x += 0x1000u; v.y += 0x1000u; v.z += 0x1000u; v.w += 0x1000u;
        ((uint4*)dst)[i] = v;
    }
}

__global__ void router_kernel(const float* __restrict__ x, const float* __restrict__ rw) {
    int t = blockIdx.x * 8 + threadIdx.y;
    int lane = threadIdx.x;
    float acc[E_NUM];
#pragma unroll
    for (int e = 0; e < E_NUM; e++) acc[e] = 0.0f;
    const float* xrow = x + (size_t)t * H_DIM;
    for (int h = lane; h < H_DIM; h += 32) {
        float xv = xrow[h];
        const float4* r = (const float4*)(rw + (size_t)h * E_NUM);
        float4 r0 = r[0], r1 = r[1];
        acc[0] += xv * r0.x; acc[1] += xv * r0.y;
        acc[2] += xv * r0.z; acc[3] += xv * r0.w;
        acc[4] += xv * r1.x; acc[5] += xv * r1.y;
        acc[6] += xv * r1.z; acc[7] += xv * r1.w;
    }
#pragma unroll
    for (int e = 0; e < E_NUM; e++) {
#pragma unroll
        for (int off = 16; off > 0; off >>= 1)
            acc[e] += __shfl_xor_sync(0xffffffffu, acc[e], off);
    }
    if (lane == 0) {
        float m = acc[0];
#pragma unroll
        for (int e = 1; e < E_NUM; e++) m = fmaxf(m, acc[e]);
        float p[E_NUM]; float s = 0.0f;
#pragma unroll
        for (int e = 0; e < E_NUM; e++) { p[e] = expf(acc[e] - m); s += p[e]; }
        float inv = 1.0f / s;
        int i1 = 0; float v1 = p[0];
#pragma unroll
        for (int e = 1; e < E_NUM; e++) if (p[e] > v1) { v1 = p[e]; i1 = e; }
        int i2 = -1; float v2 = -1.0f;
#pragma unroll
        for (int e = 0; e < E_NUM; e++) if (e != i1 && p[e] > v2) { v2 = p[e]; i2 = e; }
        int s1 = atomicAdd(&g_count[i1], 1);
        g_tok[i1 * T_TOK + s1]  = t;
        g_gate[i1 * T_TOK + s1] = v1 * inv;
        g_sel[2 * t]            = ((uint32_t)i1 << 16) | (uint32_t)s1;
        int s2 = atomicAdd(&g_count[i2], 1);
        g_tok[i2 * T_TOK + s2]  = t;
        g_gate[i2 * T_TOK + s2] = v2 * inv;
        g_sel[2 * t + 1]        = ((uint32_t)i2 << 16) | (uint32_t)s2;
    }
}

__global__ void scan_kernel() {
    if (threadIdx.x == 0) {
        int s = 0;
#pragma unroll
        for (int e = 0; e < E_NUM; e++) { g_off[e] = s; s += g_count[e]; }
    }
}

__global__ void combine_kernel(float* __restrict__ out) {
    int idx = blockIdx.x * 256 + threadIdx.x;
    int t  = idx >> 8;
    int h4 = idx & 255;
    uint32_t va = g_sel[2 * t], vb = g_sel[2 * t + 1];
    int ea = va >> 16, sa = va & 0xFFFF;
    int eb = vb >> 16, sb = vb & 0xFFFF;
    float ga = g_gate[ea * T_TOK + sa];
    float gb = g_gate[eb * T_TOK + sb];
    size_t ra = (size_t)(g_off[ea] + sa) * H_DIM + h4 * 4;
    size_t rb = (size_t)(g_off[eb] + sb) * H_DIM + h4 * 4;
    float4 ya = *(const float4*)(g_y + ra);
    float4 yb = *(const float4*)(g_y + rb);
    float4 o;
    o.x = ga * ya.x + gb * yb.x;
    o.y = ga * ya.y + gb * yb.y;
    o.z = ga * ya.z + gb * yb.z;
    o.w = ga * ya.w + gb * yb.w;
    *(float4*)(out + (size_t)t * H_DIM + h4 * 4) = o;
}

// ======================= tensor-core grouped GEMM =======================
// 128x256 tile, BK=16, 256 threads (8 warps 2Mx4N), warp tile 64x64.
// 4-stage cp.async pipeline; operands pre-rounded.
// Conflict-free consumer layouts: A m-major pitch 20; B k-major pitch 264.
#define NSTAGE   4
#define A_STRIDE 10240u                       // 128*20*4
#define B_OFF    (NSTAGE * A_STRIDE)          // 40960
#define B_STRIDE 16896u                       // 16*264*4
#define SMEM_BYTES (B_OFF + NSTAGE * B_STRIDE)   // 108544

template<int KTOT, int LDB, bool FC1>
__global__ void __launch_bounds__(256, 1)
moe_gemm(const float* __restrict__ Asrc, const float* __restrict__ W)
{
    extern __shared__ char sm[];
    const int e = blockIdx.z;
    const int n = g_count[e];
    const int row0 = blockIdx.y * 128;
    if (row0 >= n) return;
    const int col0 = blockIdx.x * 256;

    const uint32_t sbase = (uint32_t)__cvta_generic_to_shared(sm);
    const int tid = threadIdx.x;
    const int lane = tid & 31;
    const int w = tid >> 5;
    const int wm = w & 1;        // 0..1 (64 rows)
    const int wn = w >> 1;       // 0..3 (64 cols)

    // ---- producer mapping (coalesced) ----
    const int am = tid >> 1;             // A row, 2 thr/row
    const int ak = (tid & 1) * 8;
    const float* aptr = Asrc;
    uint32_t abytes = 0;
    if (row0 + am < n) {
        abytes = 16;
        if (FC1) aptr = Asrc + (size_t)g_tok[e * T_TOK + row0 + am] * H_DIM + ak;
        else     aptr = g_hidden + (size_t)(g_off[e] + row0 + am) * F_DIM + ak;
    }
    const int bk = tid >> 4;             // B k-row 0..15
    const int bn0 = (tid & 15) * 4;      // col base; chunks at +64 floats
    const float* bptr = W + (size_t)e * KTOT * LDB + (size_t)bk * LDB + col0 + bn0;

    const uint32_t dA = sbase + (uint32_t)(am * 20 + ak) * 4u;
    const uint32_t dB = sbase + B_OFF + (uint32_t)(bk * 264 + bn0) * 4u;

    auto issue = [&](int s) {
        int st = s & (NSTAGE - 1);
        int k0 = s * 16;
        uint32_t da = dA + (uint32_t)st * A_STRIDE;
        cp16(da,      aptr + k0,     abytes);
        cp16(da + 16, aptr + k0 + 4, abytes);
        uint32_t db = dB + (uint32_t)st * B_STRIDE;
        const float* bp = bptr + (size_t)k0 * LDB;
#pragma unroll
        for (int c = 0; c < 4; c++)
            cp16(db + (uint32_t)c * 256u, bp + c * 64, 16);
    };

    float acc[4][8][4];
#pragma unroll
    for (int i = 0; i < 4; i++)
#pragma unroll
        for (int j = 0; j < 8; j++)
#pragma unroll
            for (int q = 0; q < 4; q++) acc[i][j][q] = 0.0f;

    const int gq = lane >> 2;
    const int kq4 = lane & 3;

    auto compute = [&](int st) {
        const uint32_t* Asm = (const uint32_t*)(sm + st * A_STRIDE);
        const uint32_t* Bsm = (const uint32_t*)(sm + B_OFF + st * B_STRIDE);
#pragma unroll
        for (int kq = 0; kq < 16; kq += 8) {
            const int kr = kq + kq4;
            uint32_t af[4][4], bf[8][2];
#pragma unroll
            for (int mf = 0; mf < 4; mf++) {
                int m = wm * 64 + mf * 16 + gq;
                af[mf][0] = Asm[m * 20 + kr];
                af[mf][1] = Asm[(m + 8) * 20 + kr];
                af[mf][2] = Asm[m * 20 + kr + 4];
                af[mf][3] = Asm[(m + 8) * 20 + kr + 4];
            }
#pragma unroll
            for (int nf = 0; nf < 8; nf++) {
                int nn = wn * 64 + nf * 8 + gq;
                bf[nf][0] = Bsm[kr * 264 + nn];
                bf[nf][1] = Bsm[(kr + 4) * 264 + nn];
            }
#pragma unroll
            for (int mf = 0; mf < 4; mf++)
#pragma unroll
                for (int nf = 0; nf < 8; nf++)
                    mma_tf32(acc[mf][nf], af[mf], bf[nf]);
        }
    };

    constexpr int S = KTOT / 16;
    issue(0); CP_COMMIT();
    issue(1); CP_COMMIT();
    issue(2); CP_COMMIT();
#pragma unroll 1
    for (int s = 0; s < S; s++) {
        CP_WAIT(2);
        __syncthreads();
        if (s + 3 < S) issue(s + 3);
        CP_COMMIT();
        compute(s & (NSTAGE - 1));
    }

    // ---- epilogue ----
    if (FC1) {
        const int hrow0 = g_off[e];
#pragma unroll
        for (int mf = 0; mf < 4; mf++) {
            int rlo = row0 + wm * 64 + mf * 16 + gq;
            int rhi = rlo + 8;
            float* dlo = g_hidden + (size_t)(hrow0 + rlo) * F_DIM;
            float* dhi = g_hidden + (size_t)(hrow0 + rhi) * F_DIM;
#pragma unroll
            for (int nf = 0; nf < 8; nf++) {
                int c = col0 + wn * 64 + nf * 8 + 2 * kq4;
                if (rlo < n) {
                    float2 v = make_float2(rna_bits(gelu_tanh(acc[mf][nf][0])),
                                           rna_bits(gelu_tanh(acc[mf][nf][1])));
                    *(float2*)(dlo + c) = v;
                }
                if (rhi < n) {
                    float2 v = make_float2(rna_bits(gelu_tanh(acc[mf][nf][2])),
                                           rna_bits(gelu_tanh(acc[mf][nf][3])));
                    *(float2*)(dhi + c) = v;
                }
            }
        }
    } else {
        const int yrow0 = g_off[e];
#pragma unroll
        for (int mf = 0; mf < 4; mf++) {
            int rlo = row0 + wm * 64 + mf * 16 + gq;
            int rhi = rlo + 8;
            float* dlo = g_y + (size_t)(yrow0 + rlo) * H_DIM;
            float* dhi = g_y + (size_t)(yrow0 + rhi) * H_DIM;
#pragma unroll
            for (int nf = 0; nf < 8; nf++) {
                int c = col0 + wn * 64 + nf * 8 + 2 * kq4;
                if (rlo < n)
                    *(float2*)(dlo + c) = make_float2(acc[mf][nf][0], acc[mf][nf][1]);
                if (rhi < n)
                    *(float2*)(dhi + c) = make_float2(acc[mf][nf][2], acc[mf][nf][3]);
            }
        }
    }
}

// ======================= launch =======================
extern "C" void kernel_launch(void* const* d_in, const int* in_sizes, int n_in,
                              void* d_out, int out_size) {
    const float* x  = (const float*)d_in[0];
    const float* rw = (const float*)d_in[1];
    const float* w1 = (const float*)d_in[2];
    const float* w2 = (const float*)d_in[3];
    float* out = (float*)d_out;

    cudaFuncSetAttribute(moe_gemm<H_DIM, F_DIM, true>,
                         cudaFuncAttributeMaxDynamicSharedMemorySize, SMEM_BYTES);
    cudaFuncSetAttribute(moe_gemm<F_DIM, H_DIM, false>,
                         cudaFuncAttributeMaxDynamicSharedMemorySize, SMEM_BYTES);

    float* xr  = nullptr; cudaGetSymbolAddress((void**)&xr,  g_xr);
    float* w1r = nullptr; cudaGetSymbolAddress((void**)&w1r, g_w1r);
    float* w2r = nullptr; cudaGetSymbolAddress((void**)&w2r, g_w2r);

    zero_kernel<<<1, 32>>>();
    round_kernel<<<(T_TOK * H_DIM / 4 + 255) / 256, 256>>>(x, xr, T_TOK * H_DIM / 4);
    round_kernel<<<(E_NUM * H_DIM * F_DIM / 4 + 255) / 256, 256>>>(w1, w1r, E_NUM * H_DIM * F_DIM / 4);
    round_kernel<<<(E_NUM * F_DIM * H_DIM / 4 + 255) / 256, 256>>>(w2, w2r, E_NUM * F_DIM * H_DIM / 4);
    router_kernel<<<T_TOK / 8, dim3(32, 8)>>>(x, rw);
    scan_kernel<<<1, 32>>>();
    moe_gemm<H_DIM, F_DIM, true ><<<dim3(F_DIM / 256, T_TOK / 128, E_NUM), 256, SMEM_BYTES>>>(xr, w1r);
    moe_gemm<F_DIM, H_DIM, false><<<dim3(H_DIM / 256, T_TOK / 128, E_NUM), 256, SMEM_BYTES>>>(nullptr, w2r);
    combine_kernel<<<(T_TOK * H_DIM / 4) / 256, 256>>>(out);
}